// round 1
// baseline (speedup 1.0000x reference)
#include <cuda_runtime.h>
#include <cfloat>
#include <cstdint>

// Problem constants
#define S_LEN   2048
#define BATCH   2
#define HDIM    4096
#define NHEADS  32
#define HEADD   128
#define M_ROWS  4096            // B*S
#define QKV_N   12288           // 3*H
#define INV_NORM 0.08838834764831845f   // 1/sqrt(128)

// Scratch (allocation-free rule: __device__ globals)
__device__ float g_qkv[(size_t)M_ROWS * QKV_N];   // 201 MB
__device__ float g_ctx[(size_t)M_ROWS * HDIM];    // 67 MB
__device__ int   g_all_int01;
__device__ int   g_all_f01;

// ---------------------------------------------------------------------------
// Mask dtype sniffing (numpy bool may arrive as u8, i32, or f32 on the wire)
// ---------------------------------------------------------------------------
__global__ void k_set_flags() { g_all_int01 = 1; g_all_f01 = 1; }

__global__ void k_detect(const int* __restrict__ w, int n) {
    for (int i = blockIdx.x * blockDim.x + threadIdx.x; i < n;
         i += gridDim.x * blockDim.x) {
        int v = w[i];
        if ((unsigned)v > 1u) g_all_int01 = 0;
        float f = __int_as_float(v);
        if (!(f == 0.0f || f == 1.0f)) g_all_f01 = 0;
    }
}

// ---------------------------------------------------------------------------
// SGEMM (NT): C[m][n] = sum_k A[m][k] * W[n][k] + bias[n] (+ resid[m][n])
// 128x128 block, K-tile 8, 256 threads, 8x8 per-thread micro-tile.
// Sizes assumed divisible by tiles (they are: 4096 / 12288 / 4096).
// ---------------------------------------------------------------------------
__global__ __launch_bounds__(256)
void sgemm_nt(const float* __restrict__ A, const float* __restrict__ W,
              const float* __restrict__ bias, const float* __restrict__ resid,
              float* __restrict__ C, int M, int N, int K)
{
    __shared__ float As[8][128];
    __shared__ float Ws[8][128];

    const int t  = threadIdx.x;
    const int bm = blockIdx.y * 128;
    const int bn = blockIdx.x * 128;
    const int ty = t >> 4, tx = t & 15;
    const int row0 = ty * 8, col0 = tx * 8;

    // loader mapping: each thread one float4 of A and of W per K-tile
    const int lr = t >> 1;            // 0..127
    const int lk = (t & 1) << 2;      // 0 or 4
    const float* Ap = A + (size_t)(bm + lr) * K + lk;
    const float* Wp = W + (size_t)(bn + lr) * K + lk;

    float acc[8][8];
#pragma unroll
    for (int i = 0; i < 8; i++)
#pragma unroll
        for (int j = 0; j < 8; j++) acc[i][j] = 0.f;

    for (int k0 = 0; k0 < K; k0 += 8) {
        float4 av = *(const float4*)(Ap + k0);
        float4 wv = *(const float4*)(Wp + k0);
        As[lk + 0][lr] = av.x; As[lk + 1][lr] = av.y;
        As[lk + 2][lr] = av.z; As[lk + 3][lr] = av.w;
        Ws[lk + 0][lr] = wv.x; Ws[lk + 1][lr] = wv.y;
        Ws[lk + 2][lr] = wv.z; Ws[lk + 3][lr] = wv.w;
        __syncthreads();

#pragma unroll
        for (int kk = 0; kk < 8; kk++) {
            float a[8], b[8];
            *(float4*)&a[0] = *(const float4*)&As[kk][row0];
            *(float4*)&a[4] = *(const float4*)&As[kk][row0 + 4];
            *(float4*)&b[0] = *(const float4*)&Ws[kk][col0];
            *(float4*)&b[4] = *(const float4*)&Ws[kk][col0 + 4];
#pragma unroll
            for (int i = 0; i < 8; i++)
#pragma unroll
                for (int j = 0; j < 8; j++)
                    acc[i][j] = fmaf(a[i], b[j], acc[i][j]);
        }
        __syncthreads();
    }

#pragma unroll
    for (int i = 0; i < 8; i++) {
        size_t base = (size_t)(bm + row0 + i) * N + bn + col0;
#pragma unroll
        for (int j4 = 0; j4 < 8; j4 += 4) {
            float4 o;
            o.x = acc[i][j4 + 0] + bias[bn + col0 + j4 + 0];
            o.y = acc[i][j4 + 1] + bias[bn + col0 + j4 + 1];
            o.z = acc[i][j4 + 2] + bias[bn + col0 + j4 + 2];
            o.w = acc[i][j4 + 3] + bias[bn + col0 + j4 + 3];
            if (resid) {
                const float4 r = *(const float4*)(resid + base + j4);
                o.x += r.x; o.y += r.y; o.z += r.z; o.w += r.w;
            }
            *(float4*)(C + base + j4) = o;
        }
    }
}

// ---------------------------------------------------------------------------
// Flash attention: per block = (64 queries, one head). Online softmax over
// 64-key tiles. qkv layout per row: [head][3][128] interleaved (stride 384/head).
// ---------------------------------------------------------------------------
#define BQ 64
#define BKV 64
#define QKS 132   // padded row stride for sQ/sK (odd-by-4: conflict-light, 16B aligned)
#define SSS 65    // padded row stride for score tile

#define ATTN_SMEM_FLOATS (2 * BQ * QKS + BKV * HEADD + BQ * SSS + 3 * BQ)
#define ATTN_SMEM_BYTES  (ATTN_SMEM_FLOATS * 4)

__global__ __launch_bounds__(256)
void attn_kernel(const float* __restrict__ qkv, const float* __restrict__ alibi,
                 const void* __restrict__ maskp, float* __restrict__ ctx)
{
    extern __shared__ float sm[];
    float* sQ = sm;                       // 64 x 132
    float* sK = sQ + BQ * QKS;            // 64 x 132
    float* sV = sK + BKV * QKS;           // 64 x 128
    float* sS = sV + BKV * HEADD;         // 64 x 65
    float* sM = sS + BQ * SSS;            // 64 row maxes
    float* sL = sM + BQ;                  // 64 row sums
    float* sC = sL + BQ;                  // 64 corrections

    const int t    = threadIdx.x;
    const int hh   = blockIdx.y;          // b*NH + head
    const int b    = hh / NHEADS;
    const int head = hh % NHEADS;
    const int q0   = blockIdx.x * BQ;

    const int mtype = g_all_int01 ? 1 : (g_all_f01 ? 2 : 0);
    const unsigned char* mask_u8 = (const unsigned char*)maskp;
    const int*   mask_i32 = (const int*)maskp;
    const float* mask_f32 = (const float*)maskp;
    const size_t mbase = (size_t)b * S_LEN * S_LEN;

    // Load Q tile
    {
        const float* src = qkv + (size_t)(b * S_LEN + q0) * QKV_N + head * 384;
        for (int e = t; e < BQ * 32; e += 256) {
            int r = e >> 5, d4 = (e & 31) << 2;
            *(float4*)&sQ[r * QKS + d4] = *(const float4*)(src + (size_t)r * QKV_N + d4);
        }
    }
    if (t < BQ) { sM[t] = -FLT_MAX; sL[t] = 0.f; }

    float acc[8][4];
#pragma unroll
    for (int i = 0; i < 8; i++)
#pragma unroll
        for (int j = 0; j < 4; j++) acc[i][j] = 0.f;

    const int tx1 = t & 15, ty1 = t >> 4;   // phase-1 mapping (S tile)
    const int tx2 = t & 31, ty2 = t >> 5;   // phase-3 mapping (acc)
    const int r0  = ty2 * 8;

    for (int k0 = 0; k0 < S_LEN; k0 += BKV) {
        __syncthreads();   // prior-iteration reads of sK/sV/sS done
        // Load K and V tiles
        {
            const float* ksrc = qkv + (size_t)(b * S_LEN + k0) * QKV_N + head * 384 + 128;
            for (int e = t; e < BKV * 32; e += 256) {
                int r = e >> 5, d4 = (e & 31) << 2;
                float4 kv4 = *(const float4*)(ksrc + (size_t)r * QKV_N + d4);
                float4 vv4 = *(const float4*)(ksrc + (size_t)r * QKV_N + 128 + d4);
                *(float4*)&sK[r * QKS + d4]   = kv4;
                *(float4*)&sV[r * HEADD + d4] = vv4;
            }
        }
        __syncthreads();

        // Phase 1: S = Q K^T  (rows ty1+16i, cols tx1+16j)
        float s[4][4];
#pragma unroll
        for (int i = 0; i < 4; i++)
#pragma unroll
            for (int j = 0; j < 4; j++) s[i][j] = 0.f;

#pragma unroll 8
        for (int d0 = 0; d0 < HEADD; d0 += 4) {
            float4 qv[4], kv[4];
#pragma unroll
            for (int i = 0; i < 4; i++)
                qv[i] = *(const float4*)&sQ[(ty1 + 16 * i) * QKS + d0];
#pragma unroll
            for (int j = 0; j < 4; j++)
                kv[j] = *(const float4*)&sK[(tx1 + 16 * j) * QKS + d0];
#pragma unroll
            for (int i = 0; i < 4; i++)
#pragma unroll
                for (int j = 0; j < 4; j++) {
                    s[i][j] = fmaf(qv[i].x, kv[j].x, s[i][j]);
                    s[i][j] = fmaf(qv[i].y, kv[j].y, s[i][j]);
                    s[i][j] = fmaf(qv[i].z, kv[j].z, s[i][j]);
                    s[i][j] = fmaf(qv[i].w, kv[j].w, s[i][j]);
                }
        }
        // scale + alibi + mask, write score tile
#pragma unroll
        for (int j = 0; j < 4; j++) {
            const int kc = k0 + tx1 + 16 * j;
            const float al = alibi[(size_t)hh * S_LEN + kc];   // BETA = 1
#pragma unroll
            for (int i = 0; i < 4; i++) {
                const int qr = q0 + ty1 + 16 * i;
                float v = al + INV_NORM * s[i][j];
                const size_t midx = mbase + (size_t)qr * S_LEN + kc;
                bool msk;
                if (mtype == 1)      msk = (mask_i32[midx] != 0);
                else if (mtype == 2) msk = (mask_f32[midx] != 0.0f);
                else                 msk = (mask_u8[midx] != 0);
                if (msk) v = -FLT_MAX;
                sS[(ty1 + 16 * i) * SSS + (tx1 + 16 * j)] = v;
            }
        }
        __syncthreads();

        // Phase 2: online softmax row update (one thread per row)
        if (t < BQ) {
            const float mold = sM[t];
            float mx = mold;
#pragma unroll 8
            for (int k = 0; k < BKV; k++) mx = fmaxf(mx, sS[t * SSS + k]);
            const float c = __expf(mold - mx);
            float sum = 0.f;
#pragma unroll 8
            for (int k = 0; k < BKV; k++) {
                float p = __expf(sS[t * SSS + k] - mx);
                sS[t * SSS + k] = p;
                sum += p;
            }
            sM[t] = mx;
            sL[t] = sL[t] * c + sum;
            sC[t] = c;
        }
        __syncthreads();

        // Phase 3: acc = acc * c + P @ V
#pragma unroll
        for (int i = 0; i < 8; i++) {
            const float c = sC[r0 + i];
#pragma unroll
            for (int j = 0; j < 4; j++) acc[i][j] *= c;
        }
#pragma unroll 4
        for (int k = 0; k < BKV; k++) {
            const float4 v = *(const float4*)&sV[k * HEADD + tx2 * 4];
#pragma unroll
            for (int i = 0; i < 8; i++) {
                const float p = sS[(r0 + i) * SSS + k];
                acc[i][0] = fmaf(p, v.x, acc[i][0]);
                acc[i][1] = fmaf(p, v.y, acc[i][1]);
                acc[i][2] = fmaf(p, v.z, acc[i][2]);
                acc[i][3] = fmaf(p, v.w, acc[i][3]);
            }
        }
    }

    // Epilogue: ctx[b, s, head*HD + d] = acc / l
#pragma unroll
    for (int i = 0; i < 8; i++) {
        const float inv = 1.0f / sL[r0 + i];
        float4 o;
        o.x = acc[i][0] * inv; o.y = acc[i][1] * inv;
        o.z = acc[i][2] * inv; o.w = acc[i][3] * inv;
        *(float4*)&ctx[(size_t)(b * S_LEN + q0 + r0 + i) * HDIM
                       + head * HEADD + tx2 * 4] = o;
    }
}

// ---------------------------------------------------------------------------
extern "C" void kernel_launch(void* const* d_in, const int* in_sizes, int n_in,
                              void* d_out, int out_size)
{
    const float* hs    = (const float*)d_in[0];
    const float* resid = (const float*)d_in[1];
    const float* alibi = (const float*)d_in[2];
    const void*  maskp = d_in[3];
    const float* qkv_w = (const float*)d_in[4];
    const float* qkv_b = (const float*)d_in[5];
    const float* dw    = (const float*)d_in[6];
    const float* db    = (const float*)d_in[7];
    float* out = (float*)d_out;

    float *qkv_buf, *ctx_buf;
    cudaGetSymbolAddress((void**)&qkv_buf, g_qkv);
    cudaGetSymbolAddress((void**)&ctx_buf, g_ctx);

    cudaFuncSetAttribute(attn_kernel, cudaFuncAttributeMaxDynamicSharedMemorySize,
                         ATTN_SMEM_BYTES);

    // mask dtype sniff (deterministic, re-run every launch)
    k_set_flags<<<1, 1>>>();
    k_detect<<<256, 256>>>((const int*)maskp, in_sizes[3] / 4);

    // QKV projection: [4096,4096] @ [12288,4096]^T + bias -> g_qkv
    sgemm_nt<<<dim3(QKV_N / 128, M_ROWS / 128), 256>>>(
        hs, qkv_w, qkv_b, nullptr, qkv_buf, M_ROWS, QKV_N, HDIM);

    // Flash attention -> g_ctx (already in (b, s, NH*HD) layout)
    attn_kernel<<<dim3(S_LEN / BQ, BATCH * NHEADS), 256, ATTN_SMEM_BYTES>>>(
        qkv_buf, alibi, maskp, ctx_buf);

    // Output projection + bias + residual -> d_out
    sgemm_nt<<<dim3(HDIM / 128, M_ROWS / 128), 256>>>(
        ctx_buf, dw, db, resid, out, M_ROWS, HDIM, HDIM);
}

// round 2
// speedup vs baseline: 2.0449x; 2.0449x over previous
#include <cuda_runtime.h>
#include <cfloat>
#include <cstdint>

// Problem constants
#define S_LEN   2048
#define BATCH   2
#define HDIM    4096
#define NHEADS  32
#define HEADD   128
#define M_ROWS  4096            // B*S
#define QKV_N   12288           // 3*H
#define INV_NORM 0.08838834764831845f   // 1/sqrt(128)

// Scratch (allocation-free rule: __device__ globals)
__device__ float g_qkv[(size_t)M_ROWS * QKV_N];   // 201 MB
__device__ float g_ctx[(size_t)M_ROWS * HDIM];    // 67 MB
__device__ int   g_all_int01;
__device__ int   g_all_f01;

// ---------------------------------------------------------------------------
// Mask dtype sniffing (numpy bool may arrive as u8, i32, or f32 on the wire)
// ---------------------------------------------------------------------------
__global__ void k_set_flags() { g_all_int01 = 1; g_all_f01 = 1; }

__global__ void k_detect(const int* __restrict__ w, int n) {
    for (int i = blockIdx.x * blockDim.x + threadIdx.x; i < n;
         i += gridDim.x * blockDim.x) {
        int v = w[i];
        if ((unsigned)v > 1u) g_all_int01 = 0;
        float f = __int_as_float(v);
        if (!(f == 0.0f || f == 1.0f)) g_all_f01 = 0;
    }
}

// ---------------------------------------------------------------------------
// TF32 tensor-core GEMM (NT): C[m][n] = sum_k A[m][k]*W[n][k] + bias[n] (+resid)
// Block 128x128, K-tile 32, 256 threads (8 warps, 4x2), warp tile 32x64.
// mma.sync.aligned.m16n8k8.row.col.f32.tf32.tf32.f32
// ---------------------------------------------------------------------------
#define BK 32
#define LDS_PAD 36   // row stride in floats (conflict-free quad access)

__device__ __forceinline__ uint32_t f2tf32(float x) {
    uint32_t r;
    asm("cvt.rna.tf32.f32 %0, %1;" : "=r"(r) : "f"(x));
    return r;
}

__global__ __launch_bounds__(256)
void gemm_tf32(const float* __restrict__ A, const float* __restrict__ W,
               const float* __restrict__ bias, const float* __restrict__ resid,
               float* __restrict__ C, int M, int N, int K)
{
    __shared__ uint32_t As[128 * LDS_PAD];
    __shared__ uint32_t Ws[128 * LDS_PAD];

    const int t    = threadIdx.x;
    const int warp = t >> 5;
    const int lane = t & 31;
    const int gid  = lane >> 2;     // group id 0..7
    const int tig  = lane & 3;      // thread-in-group 0..3
    const int wm   = (warp >> 1) * 32;   // warp m offset (0,32,64,96)
    const int wn   = (warp & 1) * 64;    // warp n offset (0,64)

    const int bm = blockIdx.y * 128;
    const int bn = blockIdx.x * 128;

    float d[2][8][4];
#pragma unroll
    for (int i = 0; i < 2; i++)
#pragma unroll
        for (int j = 0; j < 8; j++)
#pragma unroll
            for (int c = 0; c < 4; c++) d[i][j][c] = 0.f;

    // gmem loader mapping: 128x32 tile = 1024 float4; 4 per thread
    float4 pa[4], pw[4];
#pragma unroll
    for (int i = 0; i < 4; i++) {
        const int lin = i * 256 + t;
        const int r = lin >> 3, c4 = (lin & 7) << 2;
        pa[i] = *(const float4*)(A + (size_t)(bm + r) * K + c4);
        pw[i] = *(const float4*)(W + (size_t)(bn + r) * K + c4);
    }

    for (int k0 = 0; k0 < K; k0 += BK) {
#pragma unroll
        for (int i = 0; i < 4; i++) {
            const int lin = i * 256 + t;
            const int r = lin >> 3, c4 = (lin & 7) << 2;
            uint32_t* as = &As[r * LDS_PAD + c4];
            as[0] = f2tf32(pa[i].x); as[1] = f2tf32(pa[i].y);
            as[2] = f2tf32(pa[i].z); as[3] = f2tf32(pa[i].w);
            uint32_t* ws = &Ws[r * LDS_PAD + c4];
            ws[0] = f2tf32(pw[i].x); ws[1] = f2tf32(pw[i].y);
            ws[2] = f2tf32(pw[i].z); ws[3] = f2tf32(pw[i].w);
        }
        __syncthreads();

        if (k0 + BK < K) {
#pragma unroll
            for (int i = 0; i < 4; i++) {
                const int lin = i * 256 + t;
                const int r = lin >> 3, c4 = (lin & 7) << 2;
                pa[i] = *(const float4*)(A + (size_t)(bm + r) * K + k0 + BK + c4);
                pw[i] = *(const float4*)(W + (size_t)(bn + r) * K + k0 + BK + c4);
            }
        }

#pragma unroll
        for (int kk = 0; kk < BK; kk += 8) {
            uint32_t a[2][4];
#pragma unroll
            for (int mt = 0; mt < 2; mt++) {
                const int r0 = (wm + mt * 16 + gid) * LDS_PAD;
                a[mt][0] = As[r0 + kk + tig];
                a[mt][1] = As[r0 + 8 * LDS_PAD + kk + tig];
                a[mt][2] = As[r0 + kk + tig + 4];
                a[mt][3] = As[r0 + 8 * LDS_PAD + kk + tig + 4];
            }
            uint32_t b[8][2];
#pragma unroll
            for (int nt = 0; nt < 8; nt++) {
                const int r0 = (wn + nt * 8 + gid) * LDS_PAD;
                b[nt][0] = Ws[r0 + kk + tig];
                b[nt][1] = Ws[r0 + kk + tig + 4];
            }
#pragma unroll
            for (int mt = 0; mt < 2; mt++)
#pragma unroll
                for (int nt = 0; nt < 8; nt++) {
                    asm volatile(
                        "mma.sync.aligned.m16n8k8.row.col.f32.tf32.tf32.f32 "
                        "{%0,%1,%2,%3}, {%4,%5,%6,%7}, {%8,%9}, {%0,%1,%2,%3};"
                        : "+f"(d[mt][nt][0]), "+f"(d[mt][nt][1]),
                          "+f"(d[mt][nt][2]), "+f"(d[mt][nt][3])
                        : "r"(a[mt][0]), "r"(a[mt][1]), "r"(a[mt][2]), "r"(a[mt][3]),
                          "r"(b[nt][0]), "r"(b[nt][1]));
                }
        }
        __syncthreads();
    }

    // Epilogue
#pragma unroll
    for (int mt = 0; mt < 2; mt++) {
        const int row = bm + wm + mt * 16 + gid;
#pragma unroll
        for (int nt = 0; nt < 8; nt++) {
            const int col = bn + wn + nt * 8 + tig * 2;
            const float b0 = bias[col], b1 = bias[col + 1];
            size_t i0 = (size_t)row * N + col;
            size_t i1 = (size_t)(row + 8) * N + col;
            float2 o0 = make_float2(d[mt][nt][0] + b0, d[mt][nt][1] + b1);
            float2 o1 = make_float2(d[mt][nt][2] + b0, d[mt][nt][3] + b1);
            if (resid) {
                const float2 r0 = *(const float2*)(resid + i0);
                const float2 r1 = *(const float2*)(resid + i1);
                o0.x += r0.x; o0.y += r0.y;
                o1.x += r1.x; o1.y += r1.y;
            }
            *(float2*)(C + i0) = o0;
            *(float2*)(C + i1) = o1;
        }
    }
}

// ---------------------------------------------------------------------------
// Flash attention: per block = (64 queries, one head). Online softmax over
// 64-key tiles. qkv layout per row: [head][3][128] interleaved (stride 384/head).
// ---------------------------------------------------------------------------
#define BQ 64
#define BKV 64
#define QKS 132   // padded row stride for sQ/sK
#define SSS 65    // padded row stride for score tile

#define ATTN_SMEM_FLOATS (2 * BQ * QKS + BKV * HEADD + BQ * SSS + 3 * BQ)
#define ATTN_SMEM_BYTES  (ATTN_SMEM_FLOATS * 4)

__global__ __launch_bounds__(256)
void attn_kernel(const float* __restrict__ qkv, const float* __restrict__ alibi,
                 const void* __restrict__ maskp, float* __restrict__ ctx)
{
    extern __shared__ float sm[];
    float* sQ = sm;                       // 64 x 132
    float* sK = sQ + BQ * QKS;            // 64 x 132
    float* sV = sK + BKV * QKS;           // 64 x 128
    float* sS = sV + BKV * HEADD;         // 64 x 65
    float* sM = sS + BQ * SSS;            // 64 row maxes
    float* sL = sM + BQ;                  // 64 row sums
    float* sC = sL + BQ;                  // 64 corrections

    const int t    = threadIdx.x;
    const int hh   = blockIdx.y;          // b*NH + head
    const int b    = hh / NHEADS;
    const int head = hh % NHEADS;
    const int q0   = blockIdx.x * BQ;

    const int mtype = g_all_int01 ? 1 : (g_all_f01 ? 2 : 0);
    const unsigned char* mask_u8 = (const unsigned char*)maskp;
    const int*   mask_i32 = (const int*)maskp;
    const float* mask_f32 = (const float*)maskp;
    const size_t mbase = (size_t)b * S_LEN * S_LEN;

    // Load Q tile
    {
        const float* src = qkv + (size_t)(b * S_LEN + q0) * QKV_N + head * 384;
        for (int e = t; e < BQ * 32; e += 256) {
            int r = e >> 5, d4 = (e & 31) << 2;
            *(float4*)&sQ[r * QKS + d4] = *(const float4*)(src + (size_t)r * QKV_N + d4);
        }
    }
    if (t < BQ) { sM[t] = -FLT_MAX; sL[t] = 0.f; }

    float acc[8][4];
#pragma unroll
    for (int i = 0; i < 8; i++)
#pragma unroll
        for (int j = 0; j < 4; j++) acc[i][j] = 0.f;

    const int tx1 = t & 15, ty1 = t >> 4;   // phase-1 mapping (S tile)
    const int tx2 = t & 31, ty2 = t >> 5;   // phase-3 mapping (acc)
    const int r0  = ty2 * 8;

    for (int k0 = 0; k0 < S_LEN; k0 += BKV) {
        __syncthreads();   // prior-iteration reads of sK/sV/sS done
        // Load K and V tiles
        {
            const float* ksrc = qkv + (size_t)(b * S_LEN + k0) * QKV_N + head * 384 + 128;
            for (int e = t; e < BKV * 32; e += 256) {
                int r = e >> 5, d4 = (e & 31) << 2;
                float4 kv4 = *(const float4*)(ksrc + (size_t)r * QKV_N + d4);
                float4 vv4 = *(const float4*)(ksrc + (size_t)r * QKV_N + 128 + d4);
                *(float4*)&sK[r * QKS + d4]   = kv4;
                *(float4*)&sV[r * HEADD + d4] = vv4;
            }
        }
        __syncthreads();

        // Phase 1: S = Q K^T  (rows ty1+16i, cols tx1+16j)
        float s[4][4];
#pragma unroll
        for (int i = 0; i < 4; i++)
#pragma unroll
            for (int j = 0; j < 4; j++) s[i][j] = 0.f;

#pragma unroll 8
        for (int d0 = 0; d0 < HEADD; d0 += 4) {
            float4 qv[4], kv[4];
#pragma unroll
            for (int i = 0; i < 4; i++)
                qv[i] = *(const float4*)&sQ[(ty1 + 16 * i) * QKS + d0];
#pragma unroll
            for (int j = 0; j < 4; j++)
                kv[j] = *(const float4*)&sK[(tx1 + 16 * j) * QKS + d0];
#pragma unroll
            for (int i = 0; i < 4; i++)
#pragma unroll
                for (int j = 0; j < 4; j++) {
                    s[i][j] = fmaf(qv[i].x, kv[j].x, s[i][j]);
                    s[i][j] = fmaf(qv[i].y, kv[j].y, s[i][j]);
                    s[i][j] = fmaf(qv[i].z, kv[j].z, s[i][j]);
                    s[i][j] = fmaf(qv[i].w, kv[j].w, s[i][j]);
                }
        }
        // scale + alibi + mask, write score tile
#pragma unroll
        for (int j = 0; j < 4; j++) {
            const int kc = k0 + tx1 + 16 * j;
            const float al = alibi[(size_t)hh * S_LEN + kc];   // BETA = 1
#pragma unroll
            for (int i = 0; i < 4; i++) {
                const int qr = q0 + ty1 + 16 * i;
                float v = al + INV_NORM * s[i][j];
                const size_t midx = mbase + (size_t)qr * S_LEN + kc;
                bool msk;
                if (mtype == 1)      msk = (mask_i32[midx] != 0);
                else if (mtype == 2) msk = (mask_f32[midx] != 0.0f);
                else                 msk = (mask_u8[midx] != 0);
                if (msk) v = -FLT_MAX;
                sS[(ty1 + 16 * i) * SSS + (tx1 + 16 * j)] = v;
            }
        }
        __syncthreads();

        // Phase 2: online softmax row update (4 threads per row + quad shuffle)
        {
            const int tr = t >> 2, tc = t & 3;
            const float mold = sM[tr];
            float mx = mold;
#pragma unroll 4
            for (int k = tc; k < BKV; k += 4) mx = fmaxf(mx, sS[tr * SSS + k]);
            mx = fmaxf(mx, __shfl_xor_sync(0xffffffffu, mx, 1));
            mx = fmaxf(mx, __shfl_xor_sync(0xffffffffu, mx, 2));
            float sum = 0.f;
#pragma unroll 4
            for (int k = tc; k < BKV; k += 4) {
                float p = __expf(sS[tr * SSS + k] - mx);
                sS[tr * SSS + k] = p;
                sum += p;
            }
            sum += __shfl_xor_sync(0xffffffffu, sum, 1);
            sum += __shfl_xor_sync(0xffffffffu, sum, 2);
            if (tc == 0) {
                const float c = __expf(mold - mx);
                sM[tr] = mx;
                sL[tr] = sL[tr] * c + sum;
                sC[tr] = c;
            }
        }
        __syncthreads();

        // Phase 3: acc = acc * c + P @ V
#pragma unroll
        for (int i = 0; i < 8; i++) {
            const float c = sC[r0 + i];
#pragma unroll
            for (int j = 0; j < 4; j++) acc[i][j] *= c;
        }
#pragma unroll 4
        for (int k = 0; k < BKV; k++) {
            const float4 v = *(const float4*)&sV[k * HEADD + tx2 * 4];
#pragma unroll
            for (int i = 0; i < 8; i++) {
                const float p = sS[(r0 + i) * SSS + k];
                acc[i][0] = fmaf(p, v.x, acc[i][0]);
                acc[i][1] = fmaf(p, v.y, acc[i][1]);
                acc[i][2] = fmaf(p, v.z, acc[i][2]);
                acc[i][3] = fmaf(p, v.w, acc[i][3]);
            }
        }
    }

    // Epilogue: ctx[b, s, head*HD + d] = acc / l
#pragma unroll
    for (int i = 0; i < 8; i++) {
        const float inv = 1.0f / sL[r0 + i];
        float4 o;
        o.x = acc[i][0] * inv; o.y = acc[i][1] * inv;
        o.z = acc[i][2] * inv; o.w = acc[i][3] * inv;
        *(float4*)&ctx[(size_t)(b * S_LEN + q0 + r0 + i) * HDIM
                       + head * HEADD + tx2 * 4] = o;
    }
}

// ---------------------------------------------------------------------------
extern "C" void kernel_launch(void* const* d_in, const int* in_sizes, int n_in,
                              void* d_out, int out_size)
{
    const float* hs    = (const float*)d_in[0];
    const float* resid = (const float*)d_in[1];
    const float* alibi = (const float*)d_in[2];
    const void*  maskp = d_in[3];
    const float* qkv_w = (const float*)d_in[4];
    const float* qkv_b = (const float*)d_in[5];
    const float* dw    = (const float*)d_in[6];
    const float* db    = (const float*)d_in[7];
    float* out = (float*)d_out;

    float *qkv_buf, *ctx_buf;
    cudaGetSymbolAddress((void**)&qkv_buf, g_qkv);
    cudaGetSymbolAddress((void**)&ctx_buf, g_ctx);

    cudaFuncSetAttribute(attn_kernel, cudaFuncAttributeMaxDynamicSharedMemorySize,
                         ATTN_SMEM_BYTES);

    // mask dtype sniff (deterministic, re-run every launch)
    k_set_flags<<<1, 1>>>();
    k_detect<<<256, 256>>>((const int*)maskp, in_sizes[3] / 4);

    // QKV projection: [4096,4096] @ [12288,4096]^T + bias -> g_qkv
    gemm_tf32<<<dim3(QKV_N / 128, M_ROWS / 128), 256>>>(
        hs, qkv_w, qkv_b, nullptr, qkv_buf, M_ROWS, QKV_N, HDIM);

    // Flash attention -> g_ctx (already in (b, s, NH*HD) layout)
    attn_kernel<<<dim3(S_LEN / BQ, BATCH * NHEADS), 256, ATTN_SMEM_BYTES>>>(
        qkv_buf, alibi, maskp, ctx_buf);

    // Output projection + bias + residual -> d_out
    gemm_tf32<<<dim3(HDIM / 128, M_ROWS / 128), 256>>>(
        ctx_buf, dw, db, resid, out, M_ROWS, HDIM, HDIM);
}

// round 3
// speedup vs baseline: 2.4971x; 1.2212x over previous
#include <cuda_runtime.h>
#include <cfloat>
#include <cstdint>

// Problem constants
#define S_LEN   2048
#define BATCH   2
#define HDIM    4096
#define NHEADS  32
#define HEADD   128
#define M_ROWS  4096            // B*S
#define QKV_N   12288           // 3*H
#define INV_NORM 0.08838834764831845f   // 1/sqrt(128)

// Scratch (allocation-free rule: __device__ globals)
__device__ float g_qkv[(size_t)M_ROWS * QKV_N];   // 201 MB
__device__ float g_ctx[(size_t)M_ROWS * HDIM];    // 67 MB
__device__ int   g_all_int01;
__device__ int   g_all_f01;

// ---------------------------------------------------------------------------
// Mask dtype sniffing (numpy bool may arrive as u8, i32, or f32 on the wire)
// ---------------------------------------------------------------------------
__global__ void k_set_flags() { g_all_int01 = 1; g_all_f01 = 1; }

__global__ void k_detect(const int* __restrict__ w, int n) {
    for (int i = blockIdx.x * blockDim.x + threadIdx.x; i < n;
         i += gridDim.x * blockDim.x) {
        int v = w[i];
        if ((unsigned)v > 1u) g_all_int01 = 0;
        float f = __int_as_float(v);
        if (!(f == 0.0f || f == 1.0f)) g_all_f01 = 0;
    }
}

__device__ __forceinline__ uint32_t f2tf32(float x) {
    uint32_t r;
    asm("cvt.rna.tf32.f32 %0, %1;" : "=r"(r) : "f"(x));
    return r;
}

#define MMA_TF32(D, a0, a1, a2, a3, b0, b1)                                   \
    asm volatile(                                                             \
        "mma.sync.aligned.m16n8k8.row.col.f32.tf32.tf32.f32 "                 \
        "{%0,%1,%2,%3}, {%4,%5,%6,%7}, {%8,%9}, {%0,%1,%2,%3};"               \
        : "+f"(D[0]), "+f"(D[1]), "+f"(D[2]), "+f"(D[3])                      \
        : "r"(a0), "r"(a1), "r"(a2), "r"(a3), "r"(b0), "r"(b1))

// ---------------------------------------------------------------------------
// TF32 tensor-core GEMM (NT): C[m][n] = sum_k A[m][k]*W[n][k] + bias[n] (+resid)
// Block 128x128, K-tile 32, 256 threads (8 warps, 4x2), warp tile 32x64.
// ---------------------------------------------------------------------------
#define BK 32
#define LDS_PAD 36

__global__ __launch_bounds__(256)
void gemm_tf32(const float* __restrict__ A, const float* __restrict__ W,
               const float* __restrict__ bias, const float* __restrict__ resid,
               float* __restrict__ C, int M, int N, int K)
{
    __shared__ uint32_t As[128 * LDS_PAD];
    __shared__ uint32_t Ws[128 * LDS_PAD];

    const int t    = threadIdx.x;
    const int warp = t >> 5;
    const int lane = t & 31;
    const int gid  = lane >> 2;
    const int tig  = lane & 3;
    const int wm   = (warp >> 1) * 32;
    const int wn   = (warp & 1) * 64;

    const int bm = blockIdx.y * 128;
    const int bn = blockIdx.x * 128;

    float d[2][8][4];
#pragma unroll
    for (int i = 0; i < 2; i++)
#pragma unroll
        for (int j = 0; j < 8; j++)
#pragma unroll
            for (int c = 0; c < 4; c++) d[i][j][c] = 0.f;

    float4 pa[4], pw[4];
#pragma unroll
    for (int i = 0; i < 4; i++) {
        const int lin = i * 256 + t;
        const int r = lin >> 3, c4 = (lin & 7) << 2;
        pa[i] = *(const float4*)(A + (size_t)(bm + r) * K + c4);
        pw[i] = *(const float4*)(W + (size_t)(bn + r) * K + c4);
    }

    for (int k0 = 0; k0 < K; k0 += BK) {
#pragma unroll
        for (int i = 0; i < 4; i++) {
            const int lin = i * 256 + t;
            const int r = lin >> 3, c4 = (lin & 7) << 2;
            uint32_t* as = &As[r * LDS_PAD + c4];
            as[0] = f2tf32(pa[i].x); as[1] = f2tf32(pa[i].y);
            as[2] = f2tf32(pa[i].z); as[3] = f2tf32(pa[i].w);
            uint32_t* ws = &Ws[r * LDS_PAD + c4];
            ws[0] = f2tf32(pw[i].x); ws[1] = f2tf32(pw[i].y);
            ws[2] = f2tf32(pw[i].z); ws[3] = f2tf32(pw[i].w);
        }
        __syncthreads();

        if (k0 + BK < K) {
#pragma unroll
            for (int i = 0; i < 4; i++) {
                const int lin = i * 256 + t;
                const int r = lin >> 3, c4 = (lin & 7) << 2;
                pa[i] = *(const float4*)(A + (size_t)(bm + r) * K + k0 + BK + c4);
                pw[i] = *(const float4*)(W + (size_t)(bn + r) * K + k0 + BK + c4);
            }
        }

#pragma unroll
        for (int kk = 0; kk < BK; kk += 8) {
            uint32_t a[2][4];
#pragma unroll
            for (int mt = 0; mt < 2; mt++) {
                const int r0 = (wm + mt * 16 + gid) * LDS_PAD;
                a[mt][0] = As[r0 + kk + tig];
                a[mt][1] = As[r0 + 8 * LDS_PAD + kk + tig];
                a[mt][2] = As[r0 + kk + tig + 4];
                a[mt][3] = As[r0 + 8 * LDS_PAD + kk + tig + 4];
            }
            uint32_t b[8][2];
#pragma unroll
            for (int nt = 0; nt < 8; nt++) {
                const int r0 = (wn + nt * 8 + gid) * LDS_PAD;
                b[nt][0] = Ws[r0 + kk + tig];
                b[nt][1] = Ws[r0 + kk + tig + 4];
            }
#pragma unroll
            for (int mt = 0; mt < 2; mt++)
#pragma unroll
                for (int nt = 0; nt < 8; nt++)
                    MMA_TF32(d[mt][nt], a[mt][0], a[mt][1], a[mt][2], a[mt][3],
                             b[nt][0], b[nt][1]);
        }
        __syncthreads();
    }

#pragma unroll
    for (int mt = 0; mt < 2; mt++) {
        const int row = bm + wm + mt * 16 + gid;
#pragma unroll
        for (int nt = 0; nt < 8; nt++) {
            const int col = bn + wn + nt * 8 + tig * 2;
            const float b0 = bias[col], b1 = bias[col + 1];
            size_t i0 = (size_t)row * N + col;
            size_t i1 = (size_t)(row + 8) * N + col;
            float2 o0 = make_float2(d[mt][nt][0] + b0, d[mt][nt][1] + b1);
            float2 o1 = make_float2(d[mt][nt][2] + b0, d[mt][nt][3] + b1);
            if (resid) {
                const float2 r0 = *(const float2*)(resid + i0);
                const float2 r1 = *(const float2*)(resid + i1);
                o0.x += r0.x; o0.y += r0.y;
                o1.x += r1.x; o1.y += r1.y;
            }
            *(float2*)(C + i0) = o0;
            *(float2*)(C + i1) = o1;
        }
    }
}

// ---------------------------------------------------------------------------
// Tensor-core flash attention. Block = (64 queries, one head), 8 warps.
// QK^T and P@V via mma.m16n8k8.tf32; softmax fp32 in smem.
// Warp grid 4x2: wr = warp>>1 (m), wc = warp&1 (n).
// ---------------------------------------------------------------------------
#define BQ 64
#define BKV 64
#define QS 132   // sQ row stride (uints): gid*4+tig bank-unique
#define KS 132   // sK row stride
#define VS 136   // sV row stride: tig*8+gid bank-unique
#define SS 68    // sS row stride (floats)

#define ATTN_SMEM_BYTES ((64 * QS + 64 * KS + 64 * VS + 64 * SS + 3 * 64) * 4)

__global__ __launch_bounds__(256)
void attn_tc(const float* __restrict__ qkv, const float* __restrict__ alibi,
             const void* __restrict__ maskp, float* __restrict__ ctx)
{
    extern __shared__ unsigned char smraw[];
    uint32_t* sQ = (uint32_t*)smraw;
    uint32_t* sK = sQ + 64 * QS;
    uint32_t* sV = sK + 64 * KS;
    float*    sS = (float*)(sV + 64 * VS);
    float*    sM = sS + 64 * SS;
    float*    sL = sM + 64;
    float*    sC = sL + 64;

    const int t    = threadIdx.x;
    const int warp = t >> 5, lane = t & 31;
    const int gid  = lane >> 2, tig = lane & 3;
    const int wr   = warp >> 1, wc = warp & 1;
    const int hh   = blockIdx.y;
    const int b    = hh / NHEADS;
    const int head = hh % NHEADS;
    const int q0   = blockIdx.x * BQ;

    const int mtype = g_all_int01 ? 1 : (g_all_f01 ? 2 : 0);
    const unsigned char* mask_u8 = (const unsigned char*)maskp;
    const int*   mask_i32 = (const int*)maskp;
    const float* mask_f32 = (const float*)maskp;
    const size_t mbase = (size_t)b * S_LEN * S_LEN;

    // Load Q tile (convert to tf32)
    {
        const float* src = qkv + (size_t)(b * S_LEN + q0) * QKV_N + head * 384;
        for (int e = t; e < BQ * 32; e += 256) {
            int r = e >> 5, d4 = (e & 31) << 2;
            float4 v = *(const float4*)(src + (size_t)r * QKV_N + d4);
            uint32_t* dst = &sQ[r * QS + d4];
            dst[0] = f2tf32(v.x); dst[1] = f2tf32(v.y);
            dst[2] = f2tf32(v.z); dst[3] = f2tf32(v.w);
        }
    }
    if (t < BQ) { sM[t] = -FLT_MAX; sL[t] = 0.f; }

    float o[8][4];
#pragma unroll
    for (int nt = 0; nt < 8; nt++)
#pragma unroll
        for (int c = 0; c < 4; c++) o[nt][c] = 0.f;

    const int mrow = wr * 16 + gid;     // warp-local accum row (and +8)

    for (int k0 = 0; k0 < S_LEN; k0 += BKV) {
        __syncthreads();   // prior iteration done with sK/sV/sS
        // Load K/V tiles (convert to tf32)
        {
            const float* ksrc = qkv + (size_t)(b * S_LEN + k0) * QKV_N + head * 384 + 128;
            for (int e = t; e < BKV * 32; e += 256) {
                int r = e >> 5, d4 = (e & 31) << 2;
                float4 kv4 = *(const float4*)(ksrc + (size_t)r * QKV_N + d4);
                float4 vv4 = *(const float4*)(ksrc + (size_t)r * QKV_N + 128 + d4);
                uint32_t* kd = &sK[r * KS + d4];
                kd[0] = f2tf32(kv4.x); kd[1] = f2tf32(kv4.y);
                kd[2] = f2tf32(kv4.z); kd[3] = f2tf32(kv4.w);
                uint32_t* vd = &sV[r * VS + d4];
                vd[0] = f2tf32(vv4.x); vd[1] = f2tf32(vv4.y);
                vd[2] = f2tf32(vv4.z); vd[3] = f2tf32(vv4.w);
            }
        }
        __syncthreads();

        // Phase 1: S = Q K^T  (warp tile 16x32 at rows wr*16, cols wc*32)
        float d[4][4];
#pragma unroll
        for (int nt = 0; nt < 4; nt++)
#pragma unroll
            for (int c = 0; c < 4; c++) d[nt][c] = 0.f;

#pragma unroll
        for (int kk = 0; kk < HEADD; kk += 8) {
            const uint32_t a0 = sQ[mrow * QS + kk + tig];
            const uint32_t a1 = sQ[(mrow + 8) * QS + kk + tig];
            const uint32_t a2 = sQ[mrow * QS + kk + tig + 4];
            const uint32_t a3 = sQ[(mrow + 8) * QS + kk + tig + 4];
#pragma unroll
            for (int nt = 0; nt < 4; nt++) {
                const int key = wc * 32 + nt * 8 + gid;
                const uint32_t b0 = sK[key * KS + kk + tig];
                const uint32_t b1 = sK[key * KS + kk + tig + 4];
                MMA_TF32(d[nt], a0, a1, a2, a3, b0, b1);
            }
        }

        // Epilogue: scale + alibi + mask -> sS
#pragma unroll
        for (int nt = 0; nt < 4; nt++) {
            const int colL = wc * 32 + nt * 8 + tig * 2;   // local col
            const int kc   = k0 + colL;
            const float al0 = alibi[(size_t)hh * S_LEN + kc];
            const float al1 = alibi[(size_t)hh * S_LEN + kc + 1];
            const int qrA = q0 + mrow;
            const int qrB = qrA + 8;
            float v00 = al0 + INV_NORM * d[nt][0];
            float v01 = al1 + INV_NORM * d[nt][1];
            float v10 = al0 + INV_NORM * d[nt][2];
            float v11 = al1 + INV_NORM * d[nt][3];
            const size_t mA = mbase + (size_t)qrA * S_LEN + kc;
            const size_t mB = mbase + (size_t)qrB * S_LEN + kc;
            bool k00, k01, k10, k11;
            if (mtype == 1) {
                k00 = mask_i32[mA] != 0;     k01 = mask_i32[mA + 1] != 0;
                k10 = mask_i32[mB] != 0;     k11 = mask_i32[mB + 1] != 0;
            } else if (mtype == 2) {
                k00 = mask_f32[mA] != 0.0f;  k01 = mask_f32[mA + 1] != 0.0f;
                k10 = mask_f32[mB] != 0.0f;  k11 = mask_f32[mB + 1] != 0.0f;
            } else {
                k00 = mask_u8[mA] != 0;      k01 = mask_u8[mA + 1] != 0;
                k10 = mask_u8[mB] != 0;      k11 = mask_u8[mB + 1] != 0;
            }
            if (k00) v00 = -FLT_MAX;
            if (k01) v01 = -FLT_MAX;
            if (k10) v10 = -FLT_MAX;
            if (k11) v11 = -FLT_MAX;
            *(float2*)&sS[mrow * SS + colL]       = make_float2(v00, v01);
            *(float2*)&sS[(mrow + 8) * SS + colL] = make_float2(v10, v11);
        }
        __syncthreads();

        // Phase 2: online softmax (4 threads per row)
        {
            const int tr = t >> 2, tc = t & 3;
            const float mold = sM[tr];
            float mx = mold;
#pragma unroll 4
            for (int k = tc; k < BKV; k += 4) mx = fmaxf(mx, sS[tr * SS + k]);
            mx = fmaxf(mx, __shfl_xor_sync(0xffffffffu, mx, 1));
            mx = fmaxf(mx, __shfl_xor_sync(0xffffffffu, mx, 2));
            float sum = 0.f;
#pragma unroll 4
            for (int k = tc; k < BKV; k += 4) {
                float p = __expf(sS[tr * SS + k] - mx);
                sS[tr * SS + k] = p;
                sum += p;
            }
            sum += __shfl_xor_sync(0xffffffffu, sum, 1);
            sum += __shfl_xor_sync(0xffffffffu, sum, 2);
            if (tc == 0) {
                const float c = __expf(mold - mx);
                sM[tr] = mx;
                sL[tr] = sL[tr] * c + sum;
                sC[tr] = c;
            }
        }
        __syncthreads();

        // Phase 3: O = O*c + P @ V  (warp tile 16x64 at rows wr*16, cols wc*64)
        {
            const float cA = sC[mrow];
            const float cB = sC[mrow + 8];
#pragma unroll
            for (int nt = 0; nt < 8; nt++) {
                o[nt][0] *= cA; o[nt][1] *= cA;
                o[nt][2] *= cB; o[nt][3] *= cB;
            }
#pragma unroll
            for (int kk = 0; kk < BKV; kk += 8) {
                const uint32_t a0 = f2tf32(sS[mrow * SS + kk + tig]);
                const uint32_t a1 = f2tf32(sS[(mrow + 8) * SS + kk + tig]);
                const uint32_t a2 = f2tf32(sS[mrow * SS + kk + tig + 4]);
                const uint32_t a3 = f2tf32(sS[(mrow + 8) * SS + kk + tig + 4]);
#pragma unroll
                for (int nt = 0; nt < 8; nt++) {
                    const int col = wc * 64 + nt * 8 + gid;
                    const uint32_t b0 = sV[(kk + tig) * VS + col];
                    const uint32_t b1 = sV[(kk + tig + 4) * VS + col];
                    MMA_TF32(o[nt], a0, a1, a2, a3, b0, b1);
                }
            }
        }
    }

    // Final epilogue: divide by row sums, write ctx
    {
        const float lA = 1.0f / sL[mrow];
        const float lB = 1.0f / sL[mrow + 8];
        const int rowA = b * S_LEN + q0 + mrow;
#pragma unroll
        for (int nt = 0; nt < 8; nt++) {
            const int col = head * HEADD + wc * 64 + nt * 8 + tig * 2;
            *(float2*)&ctx[(size_t)rowA * HDIM + col] =
                make_float2(o[nt][0] * lA, o[nt][1] * lA);
            *(float2*)&ctx[(size_t)(rowA + 8) * HDIM + col] =
                make_float2(o[nt][2] * lB, o[nt][3] * lB);
        }
    }
}

// ---------------------------------------------------------------------------
extern "C" void kernel_launch(void* const* d_in, const int* in_sizes, int n_in,
                              void* d_out, int out_size)
{
    const float* hs    = (const float*)d_in[0];
    const float* resid = (const float*)d_in[1];
    const float* alibi = (const float*)d_in[2];
    const void*  maskp = d_in[3];
    const float* qkv_w = (const float*)d_in[4];
    const float* qkv_b = (const float*)d_in[5];
    const float* dw    = (const float*)d_in[6];
    const float* db    = (const float*)d_in[7];
    float* out = (float*)d_out;

    float *qkv_buf, *ctx_buf;
    cudaGetSymbolAddress((void**)&qkv_buf, g_qkv);
    cudaGetSymbolAddress((void**)&ctx_buf, g_ctx);

    cudaFuncSetAttribute(attn_tc, cudaFuncAttributeMaxDynamicSharedMemorySize,
                         ATTN_SMEM_BYTES);

    // mask dtype sniff (deterministic, re-run every launch)
    k_set_flags<<<1, 1>>>();
    k_detect<<<256, 256>>>((const int*)maskp, in_sizes[3] / 4);

    // QKV projection: [4096,4096] @ [12288,4096]^T + bias -> g_qkv
    gemm_tf32<<<dim3(QKV_N / 128, M_ROWS / 128), 256>>>(
        hs, qkv_w, qkv_b, nullptr, qkv_buf, M_ROWS, QKV_N, HDIM);

    // Tensor-core flash attention -> g_ctx
    attn_tc<<<dim3(S_LEN / BQ, BATCH * NHEADS), 256, ATTN_SMEM_BYTES>>>(
        qkv_buf, alibi, maskp, ctx_buf);

    // Output projection + bias + residual -> d_out
    gemm_tf32<<<dim3(HDIM / 128, M_ROWS / 128), 256>>>(
        ctx_buf, dw, db, resid, out, M_ROWS, HDIM, HDIM);
}

// round 5
// speedup vs baseline: 3.3564x; 1.3441x over previous
#include <cuda_runtime.h>
#include <cfloat>
#include <cstdint>

// Problem constants
#define S_LEN   2048
#define BATCH   2
#define HDIM    4096
#define NHEADS  32
#define HEADD   128
#define M_ROWS  4096            // B*S
#define QKV_N   12288           // 3*H
#define INV_NORM 0.08838834764831845f   // 1/sqrt(128)

// Scratch (allocation-free rule: __device__ globals)
__device__ float g_qkv[(size_t)M_ROWS * QKV_N];   // 201 MB (rounded q,k,v)
__device__ float g_ctx[(size_t)M_ROWS * HDIM];    // 67 MB (rounded ctx)
__device__ float g_rw [(size_t)QKV_N * HDIM];     // 201 MB (rounded weights)
__device__ float g_rhs[(size_t)M_ROWS * HDIM];    // 67 MB (rounded hidden states)
__device__ int   g_all_int01;
__device__ int   g_all_f01;

// ---------------------------------------------------------------------------
// Mask dtype sniffing
// ---------------------------------------------------------------------------
__global__ void k_set_flags() { g_all_int01 = 1; g_all_f01 = 1; }

__global__ void k_detect(const int* __restrict__ w, int n) {
    for (int i = blockIdx.x * blockDim.x + threadIdx.x; i < n;
         i += gridDim.x * blockDim.x) {
        int v = w[i];
        if ((unsigned)v > 1u) g_all_int01 = 0;
        float f = __int_as_float(v);
        if (!(f == 0.0f || f == 1.0f)) g_all_f01 = 0;
    }
}

__device__ __forceinline__ uint32_t f2tf32(float x) {
    uint32_t r;
    asm("cvt.rna.tf32.f32 %0, %1;" : "=r"(r) : "f"(x));
    return r;
}
__device__ __forceinline__ float rndf(float x) {
    return __uint_as_float(f2tf32(x));
}

// Elementwise rna-round to tf32 (bit pattern stored as float)
__global__ void k_round(const float4* __restrict__ in, float4* __restrict__ out,
                        int n4) {
    for (int i = blockIdx.x * blockDim.x + threadIdx.x; i < n4;
         i += gridDim.x * blockDim.x) {
        float4 v = in[i];
        v.x = rndf(v.x); v.y = rndf(v.y); v.z = rndf(v.z); v.w = rndf(v.w);
        out[i] = v;
    }
}

// ---------------------------------------------------------------------------
// cp.async helpers
// ---------------------------------------------------------------------------
__device__ __forceinline__ void cp16(void* dst, const void* src) {
    uint32_t d = (uint32_t)__cvta_generic_to_shared(dst);
    asm volatile("cp.async.cg.shared.global [%0], [%1], 16;" :: "r"(d), "l"(src));
}
#define CP_COMMIT()  asm volatile("cp.async.commit_group;")
#define CP_WAIT(n)   asm volatile("cp.async.wait_group %0;" :: "n"(n))

// Operands are pre-rounded to tf32; raw bits go straight to the MMA.
#define MMA_TF32(D, a0, a1, a2, a3, b0, b1)                                   \
    asm volatile(                                                             \
        "mma.sync.aligned.m16n8k8.row.col.f32.tf32.tf32.f32 "                 \
        "{%0,%1,%2,%3}, {%4,%5,%6,%7}, {%8,%9}, {%0,%1,%2,%3};"               \
        : "+f"(D[0]), "+f"(D[1]), "+f"(D[2]), "+f"(D[3])                      \
        : "r"(a0), "r"(a1), "r"(a2), "r"(a3), "r"(b0), "r"(b1))

// ---------------------------------------------------------------------------
// TF32 GEMM (NT), 3-stage cp.async pipeline. Operands pre-rounded.
// Block 128x128, K-tile 32, 256 threads (8 warps, 4x2), warp tile 32x64.
// round_out != 0: round outputs to tf32 at store (for downstream MMA use).
// ---------------------------------------------------------------------------
#define BK 32
#define LDS_PAD 36
#define GTILE (128 * LDS_PAD)
#define GSTAGES 3
#define GEMM_SMEM_BYTES (GSTAGES * 2 * GTILE * 4)

__global__ __launch_bounds__(256, 2)
void gemm_tf32(const float* __restrict__ A, const float* __restrict__ W,
               const float* __restrict__ bias, const float* __restrict__ resid,
               float* __restrict__ C, int M, int N, int K, int round_out)
{
    extern __shared__ uint32_t gsm[];

    const int t    = threadIdx.x;
    const int warp = t >> 5;
    const int lane = t & 31;
    const int gid  = lane >> 2;
    const int tig  = lane & 3;
    const int wm   = (warp >> 1) * 32;
    const int wn   = (warp & 1) * 64;

    const int bm = blockIdx.y * 128;
    const int bn = blockIdx.x * 128;

    const int lr = t >> 3;               // loader row 0..31 (x4 blocks)
    const int lc = (t & 7) << 2;         // loader col (words)

    float d[2][8][4];
#pragma unroll
    for (int i = 0; i < 2; i++)
#pragma unroll
        for (int j = 0; j < 8; j++)
#pragma unroll
            for (int c = 0; c < 4; c++) d[i][j][c] = 0.f;

    const int NT = K / BK;

    auto load_stage = [&](int st, int kk0) {
        uint32_t* As = gsm + st * (2 * GTILE);
        uint32_t* Ws = As + GTILE;
#pragma unroll
        for (int i = 0; i < 4; i++) {
            const int r = i * 32 + lr;
            cp16(As + r * LDS_PAD + lc, A + (size_t)(bm + r) * K + kk0 + lc);
            cp16(Ws + r * LDS_PAD + lc, W + (size_t)(bn + r) * K + kk0 + lc);
        }
    };

    load_stage(0, 0);  CP_COMMIT();
    load_stage(1, BK); CP_COMMIT();

    for (int kt = 0; kt < NT; kt++) {
        const int s = kt % GSTAGES;
        CP_WAIT(1);
        __syncthreads();
        if (kt + 2 < NT) load_stage((kt + 2) % GSTAGES, (kt + 2) * BK);
        CP_COMMIT();

        const uint32_t* As = gsm + s * (2 * GTILE);
        const uint32_t* Ws = As + GTILE;

#pragma unroll
        for (int kk = 0; kk < BK; kk += 8) {
            uint32_t a[2][4];
#pragma unroll
            for (int mt = 0; mt < 2; mt++) {
                const int r0 = (wm + mt * 16 + gid) * LDS_PAD;
                a[mt][0] = As[r0 + kk + tig];
                a[mt][1] = As[r0 + 8 * LDS_PAD + kk + tig];
                a[mt][2] = As[r0 + kk + tig + 4];
                a[mt][3] = As[r0 + 8 * LDS_PAD + kk + tig + 4];
            }
            uint32_t b[8][2];
#pragma unroll
            for (int nt = 0; nt < 8; nt++) {
                const int r0 = (wn + nt * 8 + gid) * LDS_PAD;
                b[nt][0] = Ws[r0 + kk + tig];
                b[nt][1] = Ws[r0 + kk + tig + 4];
            }
#pragma unroll
            for (int mt = 0; mt < 2; mt++)
#pragma unroll
                for (int nt = 0; nt < 8; nt++)
                    MMA_TF32(d[mt][nt], a[mt][0], a[mt][1], a[mt][2], a[mt][3],
                             b[nt][0], b[nt][1]);
        }
    }

#pragma unroll
    for (int mt = 0; mt < 2; mt++) {
        const int row = bm + wm + mt * 16 + gid;
#pragma unroll
        for (int nt = 0; nt < 8; nt++) {
            const int col = bn + wn + nt * 8 + tig * 2;
            const float b0 = bias[col], b1 = bias[col + 1];
            size_t i0 = (size_t)row * N + col;
            size_t i1 = (size_t)(row + 8) * N + col;
            float2 o0 = make_float2(d[mt][nt][0] + b0, d[mt][nt][1] + b1);
            float2 o1 = make_float2(d[mt][nt][2] + b0, d[mt][nt][3] + b1);
            if (resid) {
                const float2 r0 = *(const float2*)(resid + i0);
                const float2 r1 = *(const float2*)(resid + i1);
                o0.x += r0.x; o0.y += r0.y;
                o1.x += r1.x; o1.y += r1.y;
            }
            if (round_out) {
                o0.x = rndf(o0.x); o0.y = rndf(o0.y);
                o1.x = rndf(o1.x); o1.y = rndf(o1.y);
            }
            *(float2*)(C + i0) = o0;
            *(float2*)(C + i1) = o1;
        }
    }
}

// ---------------------------------------------------------------------------
// Tensor-core flash attention, double-buffered K/V via cp.async,
// register-level softmax. Inputs (g_qkv) pre-rounded to tf32.
// Block = 64 queries x 1 head, 8 warps (4x2). 3 syncthreads per KV tile.
// ---------------------------------------------------------------------------
#define BQ 64
#define BKV 64
#define QS 132
#define KS 132
#define VS 136
#define SS 68
#define ATTN_NT (S_LEN / BKV)

#define OFF_SQ   0
#define OFF_SK   (OFF_SQ + 64 * QS)                 // 2 stages
#define OFF_SV   (OFF_SK + 2 * 64 * KS)             // 2 stages
#define OFF_SS   (OFF_SV + 2 * 64 * VS)
#define OFF_RED  (OFF_SS + 64 * SS)                 // 2 x 64
#define OFF_SUM  (OFF_RED + 128)                    // 2 x 64
#define OFF_SM   (OFF_SUM + 128)                    // 64
#define OFF_SL   (OFF_SM + 64)                      // 64
#define ATTN_SMEM_BYTES ((OFF_SL + 64) * 4)

__global__ __launch_bounds__(256)
void attn_tc(const float* __restrict__ qkv, const float* __restrict__ alibi,
             const void* __restrict__ maskp, float* __restrict__ ctx)
{
    extern __shared__ uint32_t asm_[];
    uint32_t* sQ   = asm_ + OFF_SQ;
    uint32_t* sK0  = asm_ + OFF_SK;
    uint32_t* sV0  = asm_ + OFF_SV;
    float*    sS   = (float*)(asm_ + OFF_SS);
    float*    sRed = (float*)(asm_ + OFF_RED);
    float*    sSum = (float*)(asm_ + OFF_SUM);
    float*    sM   = (float*)(asm_ + OFF_SM);
    float*    sL   = (float*)(asm_ + OFF_SL);

    const int t    = threadIdx.x;
    const int warp = t >> 5, lane = t & 31;
    const int gid  = lane >> 2, tig = lane & 3;
    const int wr   = warp >> 1, wc = warp & 1;
    const int hh   = blockIdx.y;
    const int b    = hh / NHEADS;
    const int head = hh % NHEADS;
    const int q0   = blockIdx.x * BQ;
    const int mrow = wr * 16 + gid;

    const int mtype = g_all_int01 ? 1 : (g_all_f01 ? 2 : 0);
    const unsigned char* mask_u8 = (const unsigned char*)maskp;
    const int*   mask_i32 = (const int*)maskp;
    const float* mask_f32 = (const float*)maskp;
    const size_t mbase = (size_t)b * S_LEN * S_LEN;

    // Q tile (pre-rounded bits)
    {
        const float* src = qkv + (size_t)(b * S_LEN + q0) * QKV_N + head * 384;
        for (int e = t; e < BQ * 32; e += 256) {
            int r = e >> 5, d4 = (e & 31) << 2;
            *(float4*)&sQ[r * QS + d4] = *(const float4*)(src + (size_t)r * QKV_N + d4);
        }
    }
    if (t < BQ) { sM[t] = -FLT_MAX; sL[t] = 0.f; }

    const float* kvbase = qkv + (size_t)b * S_LEN * QKV_N + head * 384 + 128;
    auto load_kv = [&](int st, int k0) {
        uint32_t* sK = sK0 + st * 64 * KS;
        uint32_t* sV = sV0 + st * 64 * VS;
#pragma unroll
        for (int e = t; e < BKV * 32; e += 256) {
            int r = e >> 5, d4 = (e & 31) << 2;
            const float* row = kvbase + (size_t)(k0 + r) * QKV_N + d4;
            cp16(sK + r * KS + d4, row);
            cp16(sV + r * VS + d4, row + 128);
        }
    };

    load_kv(0, 0);
    CP_COMMIT();

    float o[8][4];
#pragma unroll
    for (int nt = 0; nt < 8; nt++)
#pragma unroll
        for (int c = 0; c < 4; c++) o[nt][c] = 0.f;

    for (int kt = 0; kt < ATTN_NT; kt++) {
        const int s  = kt & 1;
        const int k0 = kt * BKV;
        CP_WAIT(0);
        __syncthreads();                         // sync1
        if (kt + 1 < ATTN_NT) load_kv(s ^ 1, k0 + BKV);
        CP_COMMIT();

        const uint32_t* sK = sK0 + s * 64 * KS;
        const uint32_t* sV = sV0 + s * 64 * VS;

        // Phase 1: S = Q K^T (warp tile 16x32)
        float d[4][4];
#pragma unroll
        for (int nt = 0; nt < 4; nt++)
#pragma unroll
            for (int c = 0; c < 4; c++) d[nt][c] = 0.f;

#pragma unroll
        for (int kk = 0; kk < HEADD; kk += 8) {
            const uint32_t a0 = sQ[mrow * QS + kk + tig];
            const uint32_t a1 = sQ[(mrow + 8) * QS + kk + tig];
            const uint32_t a2 = sQ[mrow * QS + kk + tig + 4];
            const uint32_t a3 = sQ[(mrow + 8) * QS + kk + tig + 4];
#pragma unroll
            for (int nt = 0; nt < 4; nt++) {
                const int key = wc * 32 + nt * 8 + gid;
                const uint32_t b0 = sK[key * KS + kk + tig];
                const uint32_t b1 = sK[key * KS + kk + tig + 4];
                MMA_TF32(d[nt], a0, a1, a2, a3, b0, b1);
            }
        }

        // alibi + mask in registers
#pragma unroll
        for (int nt = 0; nt < 4; nt++) {
            const int colL = wc * 32 + nt * 8 + tig * 2;
            const int kc   = k0 + colL;
            const float al0 = alibi[(size_t)hh * S_LEN + kc];
            const float al1 = alibi[(size_t)hh * S_LEN + kc + 1];
            const int qrA = q0 + mrow, qrB = qrA + 8;
            float v00 = al0 + INV_NORM * d[nt][0];
            float v01 = al1 + INV_NORM * d[nt][1];
            float v10 = al0 + INV_NORM * d[nt][2];
            float v11 = al1 + INV_NORM * d[nt][3];
            const size_t mA = mbase + (size_t)qrA * S_LEN + kc;
            const size_t mB = mbase + (size_t)qrB * S_LEN + kc;
            bool k00, k01, k10, k11;
            if (mtype == 1) {
                k00 = mask_i32[mA] != 0;     k01 = mask_i32[mA + 1] != 0;
                k10 = mask_i32[mB] != 0;     k11 = mask_i32[mB + 1] != 0;
            } else if (mtype == 2) {
                k00 = mask_f32[mA] != 0.0f;  k01 = mask_f32[mA + 1] != 0.0f;
                k10 = mask_f32[mB] != 0.0f;  k11 = mask_f32[mB + 1] != 0.0f;
            } else {
                k00 = mask_u8[mA] != 0;      k01 = mask_u8[mA + 1] != 0;
                k10 = mask_u8[mB] != 0;      k11 = mask_u8[mB + 1] != 0;
            }
            d[nt][0] = k00 ? -FLT_MAX : v00;
            d[nt][1] = k01 ? -FLT_MAX : v01;
            d[nt][2] = k10 ? -FLT_MAX : v10;
            d[nt][3] = k11 ? -FLT_MAX : v11;
        }

        // row max via quad shuffle + cross-warp exchange
        float mA = -FLT_MAX, mB = -FLT_MAX;
#pragma unroll
        for (int nt = 0; nt < 4; nt++) {
            mA = fmaxf(mA, fmaxf(d[nt][0], d[nt][1]));
            mB = fmaxf(mB, fmaxf(d[nt][2], d[nt][3]));
        }
        mA = fmaxf(mA, __shfl_xor_sync(0xffffffffu, mA, 1));
        mA = fmaxf(mA, __shfl_xor_sync(0xffffffffu, mA, 2));
        mB = fmaxf(mB, __shfl_xor_sync(0xffffffffu, mB, 1));
        mB = fmaxf(mB, __shfl_xor_sync(0xffffffffu, mB, 2));
        if (tig == 0) {
            sRed[wc * 64 + mrow]     = mA;
            sRed[wc * 64 + mrow + 8] = mB;
        }
        __syncthreads();                         // sync2

        const float moldA = sM[mrow], moldB = sM[mrow + 8];
        const float mnA = fmaxf(moldA, fmaxf(sRed[mrow], sRed[64 + mrow]));
        const float mnB = fmaxf(moldB, fmaxf(sRed[mrow + 8], sRed[64 + mrow + 8]));

        float sumA = 0.f, sumB = 0.f;
#pragma unroll
        for (int nt = 0; nt < 4; nt++) {
            const int colL = wc * 32 + nt * 8 + tig * 2;
            float p00 = __expf(d[nt][0] - mnA);
            float p01 = __expf(d[nt][1] - mnA);
            float p10 = __expf(d[nt][2] - mnB);
            float p11 = __expf(d[nt][3] - mnB);
            sumA += p00 + p01;
            sumB += p10 + p11;
            // store rna-rounded bits for the P@V MMA (sum stays unrounded)
            *(float2*)&sS[mrow * SS + colL] =
                make_float2(rndf(p00), rndf(p01));
            *(float2*)&sS[(mrow + 8) * SS + colL] =
                make_float2(rndf(p10), rndf(p11));
        }
        sumA += __shfl_xor_sync(0xffffffffu, sumA, 1);
        sumA += __shfl_xor_sync(0xffffffffu, sumA, 2);
        sumB += __shfl_xor_sync(0xffffffffu, sumB, 1);
        sumB += __shfl_xor_sync(0xffffffffu, sumB, 2);
        if (tig == 0) {
            sSum[wc * 64 + mrow]     = sumA;
            sSum[wc * 64 + mrow + 8] = sumB;
        }
        const float cA = __expf(moldA - mnA);
        const float cB = __expf(moldB - mnB);
        __syncthreads();                         // sync3

        if (wc == 0 && tig == 0) {
            sM[mrow]     = mnA;
            sM[mrow + 8] = mnB;
            sL[mrow]     = sL[mrow]     * cA + sSum[mrow]     + sSum[64 + mrow];
            sL[mrow + 8] = sL[mrow + 8] * cB + sSum[mrow + 8] + sSum[64 + mrow + 8];
        }

        // Phase 3: O = O*c + P @ V (warp tile 16x64)
#pragma unroll
        for (int nt = 0; nt < 8; nt++) {
            o[nt][0] *= cA; o[nt][1] *= cA;
            o[nt][2] *= cB; o[nt][3] *= cB;
        }
#pragma unroll
        for (int kk = 0; kk < BKV; kk += 8) {
            const uint32_t a0 = __float_as_uint(sS[mrow * SS + kk + tig]);
            const uint32_t a1 = __float_as_uint(sS[(mrow + 8) * SS + kk + tig]);
            const uint32_t a2 = __float_as_uint(sS[mrow * SS + kk + tig + 4]);
            const uint32_t a3 = __float_as_uint(sS[(mrow + 8) * SS + kk + tig + 4]);
#pragma unroll
            for (int nt = 0; nt < 8; nt++) {
                const int col = wc * 64 + nt * 8 + gid;
                const uint32_t b0 = sV[(kk + tig) * VS + col];
                const uint32_t b1 = sV[(kk + tig + 4) * VS + col];
                MMA_TF32(o[nt], a0, a1, a2, a3, b0, b1);
            }
        }
    }

    __syncthreads();                             // sL stable
    {
        const float lA = 1.0f / sL[mrow];
        const float lB = 1.0f / sL[mrow + 8];
        const int rowA = b * S_LEN + q0 + mrow;
#pragma unroll
        for (int nt = 0; nt < 8; nt++) {
            const int col = head * HEADD + wc * 64 + nt * 8 + tig * 2;
            // round ctx to tf32 so GEMM2 can consume raw bits
            *(float2*)&ctx[(size_t)rowA * HDIM + col] =
                make_float2(rndf(o[nt][0] * lA), rndf(o[nt][1] * lA));
            *(float2*)&ctx[(size_t)(rowA + 8) * HDIM + col] =
                make_float2(rndf(o[nt][2] * lB), rndf(o[nt][3] * lB));
        }
    }
}

// ---------------------------------------------------------------------------
extern "C" void kernel_launch(void* const* d_in, const int* in_sizes, int n_in,
                              void* d_out, int out_size)
{
    const float* hs    = (const float*)d_in[0];
    const float* resid = (const float*)d_in[1];
    const float* alibi = (const float*)d_in[2];
    const void*  maskp = d_in[3];
    const float* qkv_w = (const float*)d_in[4];
    const float* qkv_b = (const float*)d_in[5];
    const float* dw    = (const float*)d_in[6];
    const float* db    = (const float*)d_in[7];
    float* out = (float*)d_out;

    float *qkv_buf, *ctx_buf, *rw_buf, *rhs_buf;
    cudaGetSymbolAddress((void**)&qkv_buf, g_qkv);
    cudaGetSymbolAddress((void**)&ctx_buf, g_ctx);
    cudaGetSymbolAddress((void**)&rw_buf,  g_rw);
    cudaGetSymbolAddress((void**)&rhs_buf, g_rhs);

    cudaFuncSetAttribute(gemm_tf32, cudaFuncAttributeMaxDynamicSharedMemorySize,
                         GEMM_SMEM_BYTES);
    cudaFuncSetAttribute(attn_tc, cudaFuncAttributeMaxDynamicSharedMemorySize,
                         ATTN_SMEM_BYTES);

    k_set_flags<<<1, 1>>>();
    k_detect<<<256, 256>>>((const int*)maskp, in_sizes[3] / 4);

    // Pre-round GEMM1 operands to tf32 (rna)
    k_round<<<4096, 256>>>((const float4*)qkv_w, (float4*)rw_buf,
                           (int)((size_t)QKV_N * HDIM / 4));
    k_round<<<2048, 256>>>((const float4*)hs, (float4*)rhs_buf,
                           (int)((size_t)M_ROWS * HDIM / 4));

    // QKV projection (outputs rounded to tf32 for attention)
    gemm_tf32<<<dim3(QKV_N / 128, M_ROWS / 128), 256, GEMM_SMEM_BYTES>>>(
        rhs_buf, rw_buf, qkv_b, nullptr, qkv_buf, M_ROWS, QKV_N, HDIM, 1);

    // Pre-round dense weights (reuse rw_buf; stream-ordered after GEMM1)
    k_round<<<2048, 256>>>((const float4*)dw, (float4*)rw_buf,
                           (int)((size_t)HDIM * HDIM / 4));

    // Tensor-core flash attention -> g_ctx (rounded at store)
    attn_tc<<<dim3(S_LEN / BQ, BATCH * NHEADS), 256, ATTN_SMEM_BYTES>>>(
        qkv_buf, alibi, maskp, ctx_buf);

    // Output projection + bias + residual -> d_out (fp32 epilogue, no rounding)
    gemm_tf32<<<dim3(HDIM / 128, M_ROWS / 128), 256, GEMM_SMEM_BYTES>>>(
        ctx_buf, rw_buf, db, resid, out, M_ROWS, HDIM, HDIM, 0);
}